// round 11
// baseline (speedup 1.0000x reference)
#include <cuda_runtime.h>
#include <cuda_fp16.h>
#include <cstdint>

#define DEV_INLINE __device__ __forceinline__

static constexpr int CCH = 128;
static constexpr int NB  = 8;
static constexpr int NQ  = 4096;
static constexpr int NKV = 1024;

__device__ __half g_K[NB * NKV * CCH];  // [b][token][c]
__device__ __half g_V[NB * NKV * CCH];  // [b][token][d]

// ===================== helpers =====================
DEV_INLINE uint32_t smem_u32(const void* p) {
    uint32_t a;
    asm("{ .reg .u64 t; cvta.to.shared.u64 t, %1; cvt.u32.u64 %0, t; }" : "=r"(a) : "l"(p));
    return a;
}
DEV_INLINE void cp16(uint32_t dst, const void* src) {
    asm volatile("cp.async.cg.shared.global [%0], [%1], 16;" :: "r"(dst), "l"(src));
}
DEV_INLINE void cp_commit() { asm volatile("cp.async.commit_group;" ::: "memory"); }
DEV_INLINE void cp_wait1()  { asm volatile("cp.async.wait_group 1;" ::: "memory"); }
DEV_INLINE void cp_wait0()  { asm volatile("cp.async.wait_group 0;" ::: "memory"); }

DEV_INLINE void ldsm4(uint32_t* r, uint32_t addr) {
    asm volatile("ldmatrix.sync.aligned.m8n8.x4.shared.b16 {%0,%1,%2,%3}, [%4];"
                 : "=r"(r[0]), "=r"(r[1]), "=r"(r[2]), "=r"(r[3]) : "r"(addr));
}
DEV_INLINE void ldsm4t(uint32_t* r, uint32_t addr) {
    asm volatile("ldmatrix.sync.aligned.m8n8.x4.trans.shared.b16 {%0,%1,%2,%3}, [%4];"
                 : "=r"(r[0]), "=r"(r[1]), "=r"(r[2]), "=r"(r[3]) : "r"(addr));
}
DEV_INLINE void mma16816(float* c, uint32_t a0, uint32_t a1, uint32_t a2, uint32_t a3,
                         uint32_t b0, uint32_t b1) {
    asm volatile(
        "mma.sync.aligned.m16n8k16.row.col.f32.f16.f16.f32 "
        "{%0,%1,%2,%3},{%4,%5,%6,%7},{%8,%9},{%0,%1,%2,%3};\n"
        : "+f"(c[0]), "+f"(c[1]), "+f"(c[2]), "+f"(c[3])
        : "r"(a0), "r"(a1), "r"(a2), "r"(a3), "r"(b0), "r"(b1));
}
DEV_INLINE uint32_t packh2(float a, float b) {
    __half2 h = __floats2half2_rn(a, b);
    return *(uint32_t*)&h;
}

// stage 128xW f32 tile (row stride rs floats) -> fp16 smem rows of 256B, chunk swizzle
DEV_INLINE void stage_tile(char* dst, const float* src, int rs, int tid, int nthr) {
    for (int i = tid; i < 2048; i += nthr) {
        int r = i >> 4, cc = i & 15;
        const float4* s4 = (const float4*)(src + (size_t)r * rs + cc * 8);
        float4 lo = s4[0], hi = s4[1];
        uint4 h;
        h.x = packh2(lo.x, lo.y); h.y = packh2(lo.z, lo.w);
        h.z = packh2(hi.x, hi.y); h.w = packh2(hi.z, hi.w);
        *(uint4*)(dst + r * 256 + ((cc ^ (r & 7)) << 4)) = h;
    }
}

// 128-out x 128-in GEMM on staged tiles; A frags given; acc[16][4] out
DEV_INLINE void proj_gemm(float acc[16][4], const uint32_t xa[8][4], uint32_t wbase,
                          int lr, int lc) {
    #pragma unroll
    for (int i = 0; i < 16; i++)
        #pragma unroll
        for (int j = 0; j < 4; j++) acc[i][j] = 0.f;
    #pragma unroll
    for (int kk = 0; kk < 8; kk++) {
        #pragma unroll
        for (int db2 = 0; db2 < 8; db2++) {
            int rd = db2 * 16 + lr;
            uint32_t bf[4];
            ldsm4(bf, wbase + rd * 256 + (((2 * kk + lc) ^ (rd & 7)) << 4));
            mma16816(acc[2 * db2],     xa[kk][0], xa[kk][1], xa[kk][2], xa[kk][3], bf[0], bf[2]);
            mma16816(acc[2 * db2 + 1], xa[kk][0], xa[kk][1], xa[kk][2], xa[kk][3], bf[1], bf[3]);
        }
    }
}

// ===================== K/V projection (64 CTAs, 256 thr) =====================
static constexpr int PROJ_SMEM = 98304;
static constexpr int NKT = NB * 8;

__global__ __launch_bounds__(256, 1)
void kv_proj_kernel(const float* __restrict__ y,
                    const float* __restrict__ Wk, const float* __restrict__ bk,
                    const float* __restrict__ Wv, const float* __restrict__ bv) {
    extern __shared__ char sm[];
    const int tid = threadIdx.x, wid = tid >> 5, lane = tid & 31;
    const int g = lane >> 2, tg = lane & 3;
    const int lr = (lane & 7) + (((lane >> 3) & 1) << 3);
    const int lc = lane >> 4;
    const int b  = blockIdx.x >> 3;
    const int n0 = (blockIdx.x & 7) * 128;

    stage_tile(sm,         y + (size_t)b * CCH * NKV + n0, NKV, tid, 256);
    stage_tile(sm + 32768, Wk, CCH, tid, 256);
    stage_tile(sm + 65536, Wv, CCH, tid, 256);
    __syncthreads();

    const uint32_t sb = smem_u32(sm);
    uint32_t xa[8][4];
    {
        const int jn = wid * 2 + ((lane >> 3) & 1);
        #pragma unroll
        for (int kk = 0; kk < 8; kk++) {
            int r = kk * 16 + ((lane >> 4) & 1) * 8 + (lane & 7);
            ldsm4t(xa[kk], sb + r * 256 + ((jn ^ (r & 7)) << 4));
        }
    }

    const size_t tokBase = (size_t)b * NKV + n0 + wid * 16;
    float acc[16][4];
    #pragma unroll
    for (int pass = 0; pass < 2; pass++) {
        const float* bias = pass ? bv : bk;
        __half* outp = pass ? g_V : g_K;
        proj_gemm(acc, xa, sb + 32768 + pass * 32768, lr, lc);
        #pragma unroll
        for (int db = 0; db < 16; db++) {
            int d = db * 8 + 2 * tg;
            float bi0 = bias[d], bi1 = bias[d + 1];
            __half2 v0 = __floats2half2_rn(acc[db][0] + bi0, acc[db][1] + bi1);
            __half2 v1 = __floats2half2_rn(acc[db][2] + bi0, acc[db][3] + bi1);
            *(__half2*)&outp[(tokBase + g) * CCH + d]     = v0;
            *(__half2*)&outp[(tokBase + g + 8) * CCH + d] = v1;
        }
    }
}

// ===================== flash attention w/ inline Q projection =====================
// CTA: 64 queries, 128 threads (4 warps, 16 q each). 512 CTAs -> 2 CTAs/SM.
// SMEM: Q/x̂ 16KB | 3 KV buffers of 32KB (K 16K + V 16K). Wq staged in buf2.
static constexpr int SM_Q   = 0;
static constexpr int SM_KV0 = 16384;
static constexpr int KVB    = 32768;
static constexpr int ATTN_SMEM = SM_KV0 + 3 * KVB;  // 114688 -> 2 CTAs/SM

DEV_INLINE void load_kv(uint32_t base, int b, int kt, int tid) {
    const __half* ks = g_K + ((size_t)b * NKV + kt * 64) * CCH;
    const __half* vs = g_V + ((size_t)b * NKV + kt * 64) * CCH;
    #pragma unroll
    for (int i = tid; i < 1024; i += 128) {
        int r = i >> 4, cc = i & 15;
        uint32_t off = (uint32_t)(r * 256 + ((cc ^ (r & 7)) << 4));
        cp16(base + off,         ks + r * 128 + cc * 8);
        cp16(base + 16384 + off, vs + r * 128 + cc * 8);
    }
}

__global__ __launch_bounds__(128, 2)
void attn_kernel(const float* __restrict__ x, const float* __restrict__ Wq,
                 const float* __restrict__ bq, float* __restrict__ out) {
    extern __shared__ char smc[];
    const uint32_t sb = smem_u32(smc);
    const int tid = threadIdx.x, wid = tid >> 5, lane = tid & 31;
    const int g = lane >> 2, tg = lane & 3;
    const int b  = blockIdx.x >> 6;
    const int q0 = (blockIdx.x & 63) * 64;

    const int lr = (lane & 7) + (((lane >> 3) & 1) << 3);
    const int lc = lane >> 4;

    // async KV tiles 0,1 first (engine runs during staging)
    load_kv(sb + SM_KV0, b, 0, tid);
    cp_commit();
    load_kv(sb + SM_KV0 + KVB, b, 1, tid);
    cp_commit();

    // stage x̂ = x[b][:, q0:q0+64] into Q area: [128 c][64 n] fp16, 128B rows
    {
        const float* xsrc = x + (size_t)b * CCH * NQ + q0;
        #pragma unroll
        for (int i = tid; i < 1024; i += 128) {
            int c = i >> 3, j = i & 7;
            const float4* s4 = (const float4*)(xsrc + (size_t)c * NQ + j * 8);
            float4 lo = s4[0], hi = s4[1];
            uint4 h;
            h.x = packh2(lo.x, lo.y); h.y = packh2(lo.z, lo.w);
            h.z = packh2(hi.x, hi.y); h.w = packh2(hi.z, hi.w);
            *(uint4*)(smc + SM_Q + c * 128 + ((j ^ (c & 7)) << 4)) = h;
        }
    }
    // stage Wq into KV buffer 2 (dead once Q is computed)
    stage_tile(smc + SM_KV0 + 2 * KVB, Wq, CCH, tid, 128);
    __syncthreads();

    // Q = x̂^T Wq^T (+bq), scaled by (1/sqrt(C))*log2e, written back to Q area as fp16
    {
        uint32_t xa[8][4];
        const int jn = 2 * wid + ((lane >> 3) & 1);
        #pragma unroll
        for (int kk = 0; kk < 8; kk++) {
            int r = kk * 16 + ((lane >> 4) & 1) * 8 + (lane & 7);
            ldsm4t(xa[kk], sb + SM_Q + r * 128 + ((jn ^ (r & 7)) << 4));
        }
        float acc[16][4];
        proj_gemm(acc, xa, sb + SM_KV0 + 2 * KVB, lr, lc);
        __syncthreads();  // all x̂ reads done before overwrite

        const float qsc = 0.12751744672f;  // (1/sqrt(128)) * log2(e)
        const int qlo = wid * 16 + g, qhi = qlo + 8;
        #pragma unroll
        for (int db = 0; db < 16; db++) {
            int d = db * 8 + 2 * tg;
            float bi0 = bq[d], bi1 = bq[d + 1];
            __half2 v0 = __floats2half2_rn((acc[db][0] + bi0) * qsc, (acc[db][1] + bi1) * qsc);
            __half2 v1 = __floats2half2_rn((acc[db][2] + bi0) * qsc, (acc[db][3] + bi1) * qsc);
            *(__half2*)(smc + SM_Q + qlo * 256 + ((db ^ (qlo & 7)) << 4) + 4 * tg) = v0;
            *(__half2*)(smc + SM_Q + qhi * 256 + ((db ^ (qhi & 7)) << 4) + 4 * tg) = v1;
        }
    }
    __syncthreads();

    uint32_t qa[8][4];
    {
        const int qr = wid * 16 + lr;
        const uint32_t rowb = sb + SM_Q + qr * 256;
        const int rs = qr & 7;
        #pragma unroll
        for (int kk = 0; kk < 8; kk++) {
            int cc = 2 * kk + lc;
            ldsm4(qa[kk], rowb + ((cc ^ rs) << 4));
        }
    }

    float o[16][4];
    #pragma unroll
    for (int i = 0; i < 16; i++)
        #pragma unroll
        for (int j = 0; j < 4; j++) o[i][j] = 0.f;
    float lacc[4] = {0.f, 0.f, 0.f, 0.f};
    const uint32_t ONES = 0x3C003C00u;  // half2(1,1)

    #pragma unroll 1
    for (int kt = 0; kt < 16; kt++) {
        if (kt < 15) cp_wait1(); else cp_wait0();
        __syncthreads();

        if (kt + 2 < 16) {  // into buffer read at tile kt-1 (free now)
            load_kv(sb + SM_KV0 + ((kt + 2) % 3) * KVB, b, kt + 2, tid);
            cp_commit();
        }

        const uint32_t kb = sb + SM_KV0 + (kt % 3) * KVB;
        const uint32_t vb = kb + 16384;

        #pragma unroll
        for (int nt2 = 0; nt2 < 4; nt2++) {
            const int r = nt2 * 16 + lr;
            const int rs = r & 7;
            const uint32_t kRow = kb + r * 256;
            const uint32_t vRow = vb + r * 256;

            float s0[4], s1[4];
            #pragma unroll
            for (int j = 0; j < 4; j++) { s0[j] = 0.f; s1[j] = 0.f; }
            #pragma unroll
            for (int kk = 0; kk < 8; kk++) {
                uint32_t bf[4];
                ldsm4(bf, kRow + (((2 * kk + lc) ^ rs) << 4));
                mma16816(s0, qa[kk][0], qa[kk][1], qa[kk][2], qa[kk][3], bf[0], bf[2]);
                mma16816(s1, qa[kk][0], qa[kk][1], qa[kk][2], qa[kk][3], bf[1], bf[3]);
            }

            // scores include log2e -> bare exp2
            uint32_t a0 = packh2(exp2f(s0[0]), exp2f(s0[1]));
            uint32_t a1 = packh2(exp2f(s0[2]), exp2f(s0[3]));
            uint32_t a2 = packh2(exp2f(s1[0]), exp2f(s1[1]));
            uint32_t a3 = packh2(exp2f(s1[2]), exp2f(s1[3]));

            // row sums via all-ones MMA (accumulates across blocks and tiles)
            mma16816(lacc, a0, a1, a2, a3, ONES, ONES);

            #pragma unroll
            for (int dp = 0; dp < 8; dp++) {
                uint32_t bf[4];
                ldsm4t(bf, vRow + (((2 * dp + lc) ^ rs) << 4));
                mma16816(o[2 * dp],     a0, a1, a2, a3, bf[0], bf[1]);
                mma16816(o[2 * dp + 1], a0, a1, a2, a3, bf[2], bf[3]);
            }
        }
    }

    // ---- epilogue: normalize, transpose via SMEM, residual add, store ----
    const float inv0 = 1.f / lacc[0];  // row g sum
    const float inv8 = 1.f / lacc[2];  // row g+8 sum

    __syncthreads();
    float* OT = (float*)smc;  // [128 d][68 q]
    const int q = wid * 16 + g;
    #pragma unroll
    for (int n2 = 0; n2 < 16; n2++) {
        int d = n2 * 8 + 2 * tg;
        OT[d * 68 + q]           = o[n2][0] * inv0;
        OT[(d + 1) * 68 + q]     = o[n2][1] * inv0;
        OT[d * 68 + q + 8]       = o[n2][2] * inv8;
        OT[(d + 1) * 68 + q + 8] = o[n2][3] * inv8;
    }
    __syncthreads();

    const float* xb = x + (size_t)b * CCH * NQ + q0;
    float* ob = out + (size_t)b * CCH * NQ + q0;
    #pragma unroll
    for (int i = tid; i < 128 * 16; i += 128) {
        int d = i >> 4, j4 = (i & 15) * 4;
        float4 z  = *(float4*)&OT[d * 68 + j4];
        float4 xv = *(const float4*)&xb[(size_t)d * NQ + j4];
        float4 r  = make_float4(xv.x + z.x, xv.y + z.y, xv.z + z.z, xv.w + z.w);
        *(float4*)&ob[(size_t)d * NQ + j4] = r;
    }
}

// ===================== launch =====================
extern "C" void kernel_launch(void* const* d_in, const int* in_sizes, int n_in,
                              void* d_out, int out_size) {
    const float* x  = (const float*)d_in[0];
    const float* y  = (const float*)d_in[1];
    const float* Wq = (const float*)d_in[2];
    const float* bq = (const float*)d_in[3];
    const float* Wk = (const float*)d_in[4];
    const float* bk = (const float*)d_in[5];
    const float* Wv = (const float*)d_in[6];
    const float* bv = (const float*)d_in[7];
    float* out = (float*)d_out;

    cudaFuncSetAttribute(kv_proj_kernel, cudaFuncAttributeMaxDynamicSharedMemorySize, PROJ_SMEM);
    cudaFuncSetAttribute(attn_kernel, cudaFuncAttributeMaxDynamicSharedMemorySize, ATTN_SMEM);

    kv_proj_kernel<<<NKT, 256, PROJ_SMEM>>>(y, Wk, bk, Wv, bv);
    attn_kernel<<<NB * 64, 128, ATTN_SMEM>>>(x, Wq, bq, out);
}

// round 13
// speedup vs baseline: 1.0711x; 1.0711x over previous
#include <cuda_runtime.h>
#include <cuda_fp16.h>
#include <cstdint>

#define DEV_INLINE __device__ __forceinline__

static constexpr int CCH = 128;
static constexpr int NB  = 8;
static constexpr int NQ  = 4096;
static constexpr int NKV = 1024;

__device__ __half g_Q[NB * NQ * CCH];   // [b][token][c], scale (1/sqrt(C))*log2e folded
__device__ __half g_K[NB * NKV * CCH];  // [b][token][c]
__device__ __half g_V[NB * NKV * CCH];  // [b][token][d]

// ===================== helpers =====================
DEV_INLINE uint32_t smem_u32(const void* p) {
    uint32_t a;
    asm("{ .reg .u64 t; cvta.to.shared.u64 t, %1; cvt.u32.u64 %0, t; }" : "=r"(a) : "l"(p));
    return a;
}
DEV_INLINE void cp16(uint32_t dst, const void* src) {
    asm volatile("cp.async.cg.shared.global [%0], [%1], 16;" :: "r"(dst), "l"(src));
}
DEV_INLINE void cp_commit() { asm volatile("cp.async.commit_group;" ::: "memory"); }
DEV_INLINE void cp_wait1()  { asm volatile("cp.async.wait_group 1;" ::: "memory"); }
DEV_INLINE void cp_wait0()  { asm volatile("cp.async.wait_group 0;" ::: "memory"); }

DEV_INLINE void ldsm4(uint32_t* r, uint32_t addr) {
    asm volatile("ldmatrix.sync.aligned.m8n8.x4.shared.b16 {%0,%1,%2,%3}, [%4];"
                 : "=r"(r[0]), "=r"(r[1]), "=r"(r[2]), "=r"(r[3]) : "r"(addr));
}
DEV_INLINE void ldsm4t(uint32_t* r, uint32_t addr) {
    asm volatile("ldmatrix.sync.aligned.m8n8.x4.trans.shared.b16 {%0,%1,%2,%3}, [%4];"
                 : "=r"(r[0]), "=r"(r[1]), "=r"(r[2]), "=r"(r[3]) : "r"(addr));
}
DEV_INLINE void mma16816(float* c, uint32_t a0, uint32_t a1, uint32_t a2, uint32_t a3,
                         uint32_t b0, uint32_t b1) {
    asm volatile(
        "mma.sync.aligned.m16n8k16.row.col.f32.f16.f16.f32 "
        "{%0,%1,%2,%3},{%4,%5,%6,%7},{%8,%9},{%0,%1,%2,%3};\n"
        : "+f"(c[0]), "+f"(c[1]), "+f"(c[2]), "+f"(c[3])
        : "r"(a0), "r"(a1), "r"(a2), "r"(a3), "r"(b0), "r"(b1));
}
DEV_INLINE uint32_t packh2(float a, float b) {
    __half2 h = __floats2half2_rn(a, b);
    return *(uint32_t*)&h;
}

// ===================== fused fp16 projection =====================
// CTA: 128 tokens x 128 outputs, 256 threads (8 warps, 16 tokens each).
// bid < NB*32: Q from x. bid >= NB*32: K and V from the same staged y tile.
// SMEM: Xs (32KB) | W0 (32KB) | W1 (32KB). 2 CTAs/SM via 128-reg cap.
static constexpr int PROJ_SMEM = 98304;
static constexpr int NQT = NB * 32;   // 256 Q CTAs
static constexpr int NKT = NB * 8;    // 64 KV CTAs

DEV_INLINE void stage_tile(char* dst, const float* src, int rs, int tid) {
    #pragma unroll
    for (int i = tid; i < 2048; i += 256) {
        int r = i >> 4, cc = i & 15;
        const float4* s4 = (const float4*)(src + (size_t)r * rs + cc * 8);
        float4 lo = s4[0], hi = s4[1];
        uint4 h;
        h.x = packh2(lo.x, lo.y); h.y = packh2(lo.z, lo.w);
        h.z = packh2(hi.x, hi.y); h.w = packh2(hi.z, hi.w);
        *(uint4*)(dst + r * 256 + ((cc ^ (r & 7)) << 4)) = h;
    }
}

DEV_INLINE void proj_gemm(float acc[16][4], const uint32_t xa[8][4], uint32_t wbase,
                          int lr, int lc) {
    #pragma unroll
    for (int i = 0; i < 16; i++)
        #pragma unroll
        for (int j = 0; j < 4; j++) acc[i][j] = 0.f;
    #pragma unroll
    for (int kk = 0; kk < 8; kk++) {
        #pragma unroll
        for (int db2 = 0; db2 < 8; db2++) {
            int rd = db2 * 16 + lr;
            uint32_t bf[4];
            ldsm4(bf, wbase + rd * 256 + (((2 * kk + lc) ^ (rd & 7)) << 4));
            mma16816(acc[2 * db2],     xa[kk][0], xa[kk][1], xa[kk][2], xa[kk][3], bf[0], bf[2]);
            mma16816(acc[2 * db2 + 1], xa[kk][0], xa[kk][1], xa[kk][2], xa[kk][3], bf[1], bf[3]);
        }
    }
}

DEV_INLINE void proj_store(const float acc[16][4], __half* outp, const float* bias,
                           size_t tokBase, float sc, int g, int tg) {
    #pragma unroll
    for (int db = 0; db < 16; db++) {
        int d = db * 8 + 2 * tg;
        float bi0 = bias[d], bi1 = bias[d + 1];
        __half2 v0 = __floats2half2_rn((acc[db][0] + bi0) * sc, (acc[db][1] + bi1) * sc);
        __half2 v1 = __floats2half2_rn((acc[db][2] + bi0) * sc, (acc[db][3] + bi1) * sc);
        *(__half2*)&outp[(tokBase + g) * CCH + d]     = v0;
        *(__half2*)&outp[(tokBase + g + 8) * CCH + d] = v1;
    }
}

__global__ __launch_bounds__(256, 2)
void proj_kernel(const float* __restrict__ x, const float* __restrict__ y,
                 const float* __restrict__ Wq, const float* __restrict__ bq,
                 const float* __restrict__ Wk, const float* __restrict__ bk,
                 const float* __restrict__ Wv, const float* __restrict__ bv) {
    extern __shared__ char sm[];
    const int tid = threadIdx.x, wid = tid >> 5, lane = tid & 31;
    const int g = lane >> 2, tg = lane & 3;
    const int lr = (lane & 7) + (((lane >> 3) & 1) << 3);
    const int lc = lane >> 4;
    const int bid = blockIdx.x;

    const bool isQ = bid < NQT;
    const int b  = isQ ? (bid >> 5) : ((bid - NQT) >> 3);
    const int n0 = isQ ? ((bid & 31) * 128) : (((bid - NQT) & 7) * 128);
    const int NT = isQ ? NQ : NKV;
    const float* in = isQ ? x : y;

    stage_tile(sm, in + (size_t)b * CCH * NT + n0, NT, tid);
    if (isQ) stage_tile(sm + 32768, Wq, CCH, tid);
    else     { stage_tile(sm + 32768, Wk, CCH, tid); stage_tile(sm + 65536, Wv, CCH, tid); }
    __syncthreads();

    const uint32_t sb = smem_u32(sm);
    uint32_t xa[8][4];
    {
        const int jn = wid * 2 + ((lane >> 3) & 1);
        #pragma unroll
        for (int kk = 0; kk < 8; kk++) {
            int r = kk * 16 + ((lane >> 4) & 1) * 8 + (lane & 7);
            ldsm4t(xa[kk], sb + r * 256 + ((jn ^ (r & 7)) << 4));
        }
    }

    const size_t tokBase = (size_t)b * NT + n0 + wid * 16;
    float acc[16][4];
    if (isQ) {
        proj_gemm(acc, xa, sb + 32768, lr, lc);
        const float qsc = 0.12751744672f;  // (1/sqrt(128)) * log2(e)
        proj_store(acc, g_Q, bq, tokBase, qsc, g, tg);
    } else {
        proj_gemm(acc, xa, sb + 32768, lr, lc);
        proj_store(acc, g_K, bk, tokBase, 1.0f, g, tg);
        proj_gemm(acc, xa, sb + 65536, lr, lc);
        proj_store(acc, g_V, bv, tokBase, 1.0f, g, tg);
    }
}

// ===================== fp16 flash attention =====================
// CTA: 128 queries x full 128 d, 8 warps. 256 CTAs; 2 CTAs/SM (96KB smem, 128 regs).
static constexpr int SM_Q   = 0;
static constexpr int SM_KV0 = 32768;
static constexpr int KVB    = 32768;
static constexpr int ATTN_SMEM = SM_KV0 + 2 * KVB;  // 98304 -> 2 CTAs/SM

DEV_INLINE void load_kv(uint32_t base, int b, int kt, int tid) {
    const __half* ks = g_K + ((size_t)b * NKV + kt * 64) * CCH;
    const __half* vs = g_V + ((size_t)b * NKV + kt * 64) * CCH;
    #pragma unroll
    for (int i = tid; i < 1024; i += 256) {
        int r = i >> 4, cc = i & 15;
        uint32_t off = (uint32_t)(r * 256 + ((cc ^ (r & 7)) << 4));
        cp16(base + off,         ks + r * 128 + cc * 8);
        cp16(base + 16384 + off, vs + r * 128 + cc * 8);
    }
}

__global__ __launch_bounds__(256, 2)
void attn_kernel(const float* __restrict__ x, float* __restrict__ out) {
    extern __shared__ char smc[];
    const uint32_t sb = smem_u32(smc);
    const int tid = threadIdx.x, wid = tid >> 5, lane = tid & 31;
    const int g = lane >> 2, tg = lane & 3;
    const int b  = blockIdx.x >> 5;
    const int q0 = (blockIdx.x & 31) * 128;

    const int lr = (lane & 7) + (((lane >> 3) & 1) << 3);
    const int lc = lane >> 4;

    // prologue: group0 = {Q, KV tile 0}
    {
        const __half* qsrc = g_Q + ((size_t)b * NQ + q0) * CCH;
        #pragma unroll
        for (int i = tid; i < 2048; i += 256) {
            int r = i >> 4, cc = i & 15;
            uint32_t off = (uint32_t)(r * 256 + ((cc ^ (r & 7)) << 4));
            cp16(sb + SM_Q + off, qsrc + r * 128 + cc * 8);
        }
        load_kv(sb + SM_KV0, b, 0, tid);
        cp_commit();
    }

    uint32_t qa[8][4];
    float o[16][4];
    #pragma unroll
    for (int i = 0; i < 16; i++)
        #pragma unroll
        for (int j = 0; j < 4; j++) o[i][j] = 0.f;
    float lacc[4] = {0.f, 0.f, 0.f, 0.f};
    const uint32_t ONES = 0x3C003C00u;  // half2(1,1)

    #pragma unroll 1
    for (int kt = 0; kt < 16; kt++) {
        __syncthreads();  // all warps done reading buf (kt+1)&1 (tile kt-1)
        if (kt < 15) {
            load_kv(sb + SM_KV0 + ((kt + 1) & 1) * KVB, b, kt + 1, tid);
            cp_commit();
            cp_wait1();
        } else {
            cp_wait0();
        }
        __syncthreads();  // buf kt&1 visible

        if (kt == 0) {  // Q fragments (once)
            const int qr = wid * 16 + lr;
            const uint32_t rowb = sb + SM_Q + qr * 256;
            const int rs = qr & 7;
            #pragma unroll
            for (int kk = 0; kk < 8; kk++) {
                int cc = 2 * kk + lc;
                ldsm4(qa[kk], rowb + ((cc ^ rs) << 4));
            }
        }

        const uint32_t kb = sb + SM_KV0 + (kt & 1) * KVB;
        const uint32_t vb = kb + 16384;

        // per 16-key block: S-MMA -> exp2 -> ones-MMA row sum -> PV-MMA
        #pragma unroll
        for (int nt2 = 0; nt2 < 4; nt2++) {
            const int r = nt2 * 16 + lr;
            const int rs = r & 7;
            const uint32_t kRow = kb + r * 256;
            const uint32_t vRow = vb + r * 256;

            float s0[4], s1[4];
            #pragma unroll
            for (int j = 0; j < 4; j++) { s0[j] = 0.f; s1[j] = 0.f; }
            #pragma unroll
            for (int kk = 0; kk < 8; kk++) {
                uint32_t bf[4];
                ldsm4(bf, kRow + (((2 * kk + lc) ^ rs) << 4));
                mma16816(s0, qa[kk][0], qa[kk][1], qa[kk][2], qa[kk][3], bf[0], bf[2]);
                mma16816(s1, qa[kk][0], qa[kk][1], qa[kk][2], qa[kk][3], bf[1], bf[3]);
            }

            // scores include log2e -> bare exp2
            uint32_t a0 = packh2(exp2f(s0[0]), exp2f(s0[1]));
            uint32_t a1 = packh2(exp2f(s0[2]), exp2f(s0[3]));
            uint32_t a2 = packh2(exp2f(s1[0]), exp2f(s1[1]));
            uint32_t a3 = packh2(exp2f(s1[2]), exp2f(s1[3]));

            // row sums via all-ones MMA (accumulates across blocks and tiles)
            mma16816(lacc, a0, a1, a2, a3, ONES, ONES);

            #pragma unroll
            for (int dp = 0; dp < 8; dp++) {
                uint32_t bf[4];
                ldsm4t(bf, vRow + (((2 * dp + lc) ^ rs) << 4));
                mma16816(o[2 * dp],     a0, a1, a2, a3, bf[0], bf[1]);
                mma16816(o[2 * dp + 1], a0, a1, a2, a3, bf[2], bf[3]);
            }
        }
    }

    // ---- epilogue: normalize (ones-MMA sums), transpose via SMEM, residual ----
    const float inv0 = 1.f / lacc[0];  // row g
    const float inv8 = 1.f / lacc[2];  // row g+8

    __syncthreads();
    float* OT = (float*)smc;  // [128 d][132 q]
    const int q = wid * 16 + g;
    #pragma unroll
    for (int n2 = 0; n2 < 16; n2++) {
        int d = n2 * 8 + 2 * tg;
        OT[d * 132 + q]           = o[n2][0] * inv0;
        OT[(d + 1) * 132 + q]     = o[n2][1] * inv0;
        OT[d * 132 + q + 8]       = o[n2][2] * inv8;
        OT[(d + 1) * 132 + q + 8] = o[n2][3] * inv8;
    }
    __syncthreads();

    const float* xb = x + (size_t)b * CCH * NQ + q0;
    float* ob = out + (size_t)b * CCH * NQ + q0;
    #pragma unroll
    for (int i = tid; i < 128 * 32; i += 256) {
        int d = i >> 5, j4 = (i & 31) * 4;
        float4 z  = *(float4*)&OT[d * 132 + j4];
        float4 xv = *(const float4*)&xb[(size_t)d * NQ + j4];
        float4 r  = make_float4(xv.x + z.x, xv.y + z.y, xv.z + z.z, xv.w + z.w);
        *(float4*)&ob[(size_t)d * NQ + j4] = r;
    }
}

// ===================== launch =====================
extern "C" void kernel_launch(void* const* d_in, const int* in_sizes, int n_in,
                              void* d_out, int out_size) {
    const float* x  = (const float*)d_in[0];
    const float* y  = (const float*)d_in[1];
    const float* Wq = (const float*)d_in[2];
    const float* bq = (const float*)d_in[3];
    const float* Wk = (const float*)d_in[4];
    const float* bk = (const float*)d_in[5];
    const float* Wv = (const float*)d_in[6];
    const float* bv = (const float*)d_in[7];
    float* out = (float*)d_out;

    cudaFuncSetAttribute(proj_kernel, cudaFuncAttributeMaxDynamicSharedMemorySize, PROJ_SMEM);
    cudaFuncSetAttribute(attn_kernel, cudaFuncAttributeMaxDynamicSharedMemorySize, ATTN_SMEM);

    proj_kernel<<<NQT + NKT, 256, PROJ_SMEM>>>(x, y, Wq, bq, Wk, bk, Wv, bv);
    attn_kernel<<<NB * 32, 256, ATTN_SMEM>>>(x, out);
}

// round 14
// speedup vs baseline: 1.0899x; 1.0176x over previous
#include <cuda_runtime.h>
#include <cuda_fp16.h>
#include <cstdint>

#define DEV_INLINE __device__ __forceinline__

static constexpr int CCH = 128;
static constexpr int NB  = 8;
static constexpr int NQ  = 4096;
static constexpr int NKV = 1024;

__device__ __half g_Q[NB * NQ * CCH];   // [b][token][c], scale (1/sqrt(C))*log2e folded
__device__ __half g_K[NB * NKV * CCH];  // [b][token][c]
__device__ __half g_V[NB * NKV * CCH];  // [b][token][d]

// cross-phase sync (zero-init; self-resetting each launch)
__device__ int g_done[NB];
__device__ int g_attn_done;

// ===================== helpers =====================
DEV_INLINE uint32_t smem_u32(const void* p) {
    uint32_t a;
    asm("{ .reg .u64 t; cvta.to.shared.u64 t, %1; cvt.u32.u64 %0, t; }" : "=r"(a) : "l"(p));
    return a;
}
DEV_INLINE void cp16(uint32_t dst, const void* src) {
    asm volatile("cp.async.cg.shared.global [%0], [%1], 16;" :: "r"(dst), "l"(src));
}
DEV_INLINE void cp_commit() { asm volatile("cp.async.commit_group;" ::: "memory"); }
DEV_INLINE void cp_wait1()  { asm volatile("cp.async.wait_group 1;" ::: "memory"); }
DEV_INLINE void cp_wait0()  { asm volatile("cp.async.wait_group 0;" ::: "memory"); }

DEV_INLINE void ldsm4(uint32_t* r, uint32_t addr) {
    asm volatile("ldmatrix.sync.aligned.m8n8.x4.shared.b16 {%0,%1,%2,%3}, [%4];"
                 : "=r"(r[0]), "=r"(r[1]), "=r"(r[2]), "=r"(r[3]) : "r"(addr));
}
DEV_INLINE void ldsm4t(uint32_t* r, uint32_t addr) {
    asm volatile("ldmatrix.sync.aligned.m8n8.x4.trans.shared.b16 {%0,%1,%2,%3}, [%4];"
                 : "=r"(r[0]), "=r"(r[1]), "=r"(r[2]), "=r"(r[3]) : "r"(addr));
}
DEV_INLINE void mma16816(float* c, uint32_t a0, uint32_t a1, uint32_t a2, uint32_t a3,
                         uint32_t b0, uint32_t b1) {
    asm volatile(
        "mma.sync.aligned.m16n8k16.row.col.f32.f16.f16.f32 "
        "{%0,%1,%2,%3},{%4,%5,%6,%7},{%8,%9},{%0,%1,%2,%3};\n"
        : "+f"(c[0]), "+f"(c[1]), "+f"(c[2]), "+f"(c[3])
        : "r"(a0), "r"(a1), "r"(a2), "r"(a3), "r"(b0), "r"(b1));
}
DEV_INLINE uint32_t packh2(float a, float b) {
    __half2 h = __floats2half2_rn(a, b);
    return *(uint32_t*)&h;
}
DEV_INLINE uint32_t ld_acq(const int* p) {
    uint32_t v;
    asm volatile("ld.acquire.gpu.global.u32 %0, [%1];" : "=r"(v) : "l"(p) : "memory");
    return v;
}

// ===================== shared building blocks =====================
DEV_INLINE void stage_tile(char* dst, const float* src, int rs, int tid) {
    #pragma unroll
    for (int i = tid; i < 2048; i += 256) {
        int r = i >> 4, cc = i & 15;
        const float4* s4 = (const float4*)(src + (size_t)r * rs + cc * 8);
        float4 lo = s4[0], hi = s4[1];
        uint4 h;
        h.x = packh2(lo.x, lo.y); h.y = packh2(lo.z, lo.w);
        h.z = packh2(hi.x, hi.y); h.w = packh2(hi.z, hi.w);
        *(uint4*)(dst + r * 256 + ((cc ^ (r & 7)) << 4)) = h;
    }
}

DEV_INLINE void proj_gemm(float acc[16][4], const uint32_t xa[8][4], uint32_t wbase,
                          int lr, int lc) {
    #pragma unroll
    for (int i = 0; i < 16; i++)
        #pragma unroll
        for (int j = 0; j < 4; j++) acc[i][j] = 0.f;
    #pragma unroll
    for (int kk = 0; kk < 8; kk++) {
        #pragma unroll
        for (int db2 = 0; db2 < 8; db2++) {
            int rd = db2 * 16 + lr;
            uint32_t bf[4];
            ldsm4(bf, wbase + rd * 256 + (((2 * kk + lc) ^ (rd & 7)) << 4));
            mma16816(acc[2 * db2],     xa[kk][0], xa[kk][1], xa[kk][2], xa[kk][3], bf[0], bf[2]);
            mma16816(acc[2 * db2 + 1], xa[kk][0], xa[kk][1], xa[kk][2], xa[kk][3], bf[1], bf[3]);
        }
    }
}

DEV_INLINE void proj_store(const float acc[16][4], __half* outp, const float* bias,
                           size_t tokBase, float sc, int g, int tg) {
    #pragma unroll
    for (int db = 0; db < 16; db++) {
        int d = db * 8 + 2 * tg;
        float bi0 = bias[d], bi1 = bias[d + 1];
        __half2 v0 = __floats2half2_rn((acc[db][0] + bi0) * sc, (acc[db][1] + bi1) * sc);
        __half2 v1 = __floats2half2_rn((acc[db][2] + bi0) * sc, (acc[db][3] + bi1) * sc);
        *(__half2*)&outp[(tokBase + g) * CCH + d]     = v0;
        *(__half2*)&outp[(tokBase + g + 8) * CCH + d] = v1;
    }
}

// attn smem layout
static constexpr int SM_Q   = 0;
static constexpr int SM_KV0 = 32768;
static constexpr int KVB    = 32768;
static constexpr int FUSED_SMEM = 98304;  // 96KB both phases -> 2 CTAs/SM

DEV_INLINE void load_kv(uint32_t base, int b, int kt, int tid) {
    const __half* ks = g_K + ((size_t)b * NKV + kt * 64) * CCH;
    const __half* vs = g_V + ((size_t)b * NKV + kt * 64) * CCH;
    #pragma unroll
    for (int i = tid; i < 1024; i += 256) {
        int r = i >> 4, cc = i & 15;
        uint32_t off = (uint32_t)(r * 256 + ((cc ^ (r & 7)) << 4));
        cp16(base + off,         ks + r * 128 + cc * 8);
        cp16(base + 16384 + off, vs + r * 128 + cc * 8);
    }
}

// grid: 320 proj CTAs (batch-major: b*40 + j, j<32 Q-tile, j>=32 KV-tile) then 256 attn
static constexpr int PROJ_CTAS = NB * 40;  // 320
static constexpr int ATTN_CTAS = NB * 32;  // 256

__global__ __launch_bounds__(256, 2)
void fused_kernel(const float* __restrict__ x, const float* __restrict__ y,
                  const float* __restrict__ Wq, const float* __restrict__ bq,
                  const float* __restrict__ Wk, const float* __restrict__ bk,
                  const float* __restrict__ Wv, const float* __restrict__ bv,
                  float* __restrict__ out) {
    extern __shared__ char smc[];
    const uint32_t sb = smem_u32(smc);
    const int tid = threadIdx.x, wid = tid >> 5, lane = tid & 31;
    const int g = lane >> 2, tg = lane & 3;
    const int lr = (lane & 7) + (((lane >> 3) & 1) << 3);
    const int lc = lane >> 4;

    if (blockIdx.x < PROJ_CTAS) {
        // ================= projection phase =================
        const int b = blockIdx.x / 40;
        const int j = blockIdx.x % 40;
        const bool isQ = j < 32;
        const int n0 = (isQ ? j : (j - 32)) * 128;
        const int NT = isQ ? NQ : NKV;
        const float* in = isQ ? x : y;

        stage_tile(smc, in + (size_t)b * CCH * NT + n0, NT, tid);
        if (isQ) stage_tile(smc + 32768, Wq, CCH, tid);
        else     { stage_tile(smc + 32768, Wk, CCH, tid); stage_tile(smc + 65536, Wv, CCH, tid); }
        __syncthreads();

        uint32_t xa[8][4];
        {
            const int jn = wid * 2 + ((lane >> 3) & 1);
            #pragma unroll
            for (int kk = 0; kk < 8; kk++) {
                int r = kk * 16 + ((lane >> 4) & 1) * 8 + (lane & 7);
                ldsm4t(xa[kk], sb + r * 256 + ((jn ^ (r & 7)) << 4));
            }
        }

        const size_t tokBase = (size_t)b * NT + n0 + wid * 16;
        float acc[16][4];
        if (isQ) {
            proj_gemm(acc, xa, sb + 32768, lr, lc);
            const float qsc = 0.12751744672f;  // (1/sqrt(128)) * log2(e)
            proj_store(acc, g_Q, bq, tokBase, qsc, g, tg);
        } else {
            proj_gemm(acc, xa, sb + 32768, lr, lc);
            proj_store(acc, g_K, bk, tokBase, 1.0f, g, tg);
            proj_gemm(acc, xa, sb + 65536, lr, lc);
            proj_store(acc, g_V, bv, tokBase, 1.0f, g, tg);
        }

        __syncthreads();          // all stores issued by all threads
        if (tid == 0) {
            __threadfence();      // release
            atomicAdd(&g_done[b], 1);
        }
        return;
    }

    // ================= attention phase =================
    const int abid = blockIdx.x - PROJ_CTAS;
    const int b  = abid >> 5;
    const int q0 = (abid & 31) * 128;

    // wait for this batch's 40 proj CTAs (acquire pairs with producer release)
    if (tid == 0) {
        while (ld_acq(&g_done[b]) < 40u) __nanosleep(128);
    }
    __syncthreads();

    // prologue: group0 = {Q, KV tile 0}
    {
        const __half* qsrc = g_Q + ((size_t)b * NQ + q0) * CCH;
        #pragma unroll
        for (int i = tid; i < 2048; i += 256) {
            int r = i >> 4, cc = i & 15;
            uint32_t off = (uint32_t)(r * 256 + ((cc ^ (r & 7)) << 4));
            cp16(sb + SM_Q + off, qsrc + r * 128 + cc * 8);
        }
        load_kv(sb + SM_KV0, b, 0, tid);
        cp_commit();
    }

    uint32_t qa[8][4];
    float o[16][4];
    #pragma unroll
    for (int i = 0; i < 16; i++)
        #pragma unroll
        for (int j = 0; j < 4; j++) o[i][j] = 0.f;
    float l0 = 0.f, l8 = 0.f;

    #pragma unroll 1
    for (int kt = 0; kt < 16; kt++) {
        __syncthreads();  // all warps done reading buf (kt+1)&1 (tile kt-1)
        if (kt < 15) {
            load_kv(sb + SM_KV0 + ((kt + 1) & 1) * KVB, b, kt + 1, tid);
            cp_commit();
            cp_wait1();
        } else {
            cp_wait0();
        }
        __syncthreads();  // buf kt&1 visible

        if (kt == 0) {  // Q fragments (once)
            const int qr = wid * 16 + lr;
            const uint32_t rowb = sb + SM_Q + qr * 256;
            const int rs = qr & 7;
            #pragma unroll
            for (int kk = 0; kk < 8; kk++) {
                int cc = 2 * kk + lc;
                ldsm4(qa[kk], rowb + ((cc ^ rs) << 4));
            }
        }

        const uint32_t kb = sb + SM_KV0 + (kt & 1) * KVB;
        const uint32_t vb = kb + 16384;

        // per 16-key block: S-MMA -> exp2 -> fadd row sums -> PV-MMA
        #pragma unroll
        for (int nt2 = 0; nt2 < 4; nt2++) {
            const int r = nt2 * 16 + lr;
            const int rs = r & 7;
            const uint32_t kRow = kb + r * 256;
            const uint32_t vRow = vb + r * 256;

            float s0[4], s1[4];
            #pragma unroll
            for (int j = 0; j < 4; j++) { s0[j] = 0.f; s1[j] = 0.f; }
            #pragma unroll
            for (int kk = 0; kk < 8; kk++) {
                uint32_t bf[4];
                ldsm4(bf, kRow + (((2 * kk + lc) ^ rs) << 4));
                mma16816(s0, qa[kk][0], qa[kk][1], qa[kk][2], qa[kk][3], bf[0], bf[2]);
                mma16816(s1, qa[kk][0], qa[kk][1], qa[kk][2], qa[kk][3], bf[1], bf[3]);
            }

            // scores include log2e -> bare exp2; row sums on fma pipe
            float e00 = exp2f(s0[0]), e01 = exp2f(s0[1]), e02 = exp2f(s0[2]), e03 = exp2f(s0[3]);
            float e10 = exp2f(s1[0]), e11 = exp2f(s1[1]), e12 = exp2f(s1[2]), e13 = exp2f(s1[3]);
            l0 += (e00 + e01) + (e10 + e11);
            l8 += (e02 + e03) + (e12 + e13);
            uint32_t a0 = packh2(e00, e01), a1 = packh2(e02, e03);
            uint32_t a2 = packh2(e10, e11), a3 = packh2(e12, e13);

            #pragma unroll
            for (int dp = 0; dp < 8; dp++) {
                uint32_t bf[4];
                ldsm4t(bf, vRow + (((2 * dp + lc) ^ rs) << 4));
                mma16816(o[2 * dp],     a0, a1, a2, a3, bf[0], bf[1]);
                mma16816(o[2 * dp + 1], a0, a1, a2, a3, bf[2], bf[3]);
            }
        }
    }

    // ---- epilogue: reduce sums over quad, normalize, transpose, residual ----
    l0 += __shfl_xor_sync(0xffffffffu, l0, 1);
    l0 += __shfl_xor_sync(0xffffffffu, l0, 2);
    l8 += __shfl_xor_sync(0xffffffffu, l8, 1);
    l8 += __shfl_xor_sync(0xffffffffu, l8, 2);
    const float inv0 = 1.f / l0, inv8 = 1.f / l8;

    __syncthreads();
    float* OT = (float*)smc;  // [128 d][132 q]
    const int q = wid * 16 + g;
    #pragma unroll
    for (int n2 = 0; n2 < 16; n2++) {
        int d = n2 * 8 + 2 * tg;
        OT[d * 132 + q]           = o[n2][0] * inv0;
        OT[(d + 1) * 132 + q]     = o[n2][1] * inv0;
        OT[d * 132 + q + 8]       = o[n2][2] * inv8;
        OT[(d + 1) * 132 + q + 8] = o[n2][3] * inv8;
    }
    __syncthreads();

    const float* xb = x + (size_t)b * CCH * NQ + q0;
    float* ob = out + (size_t)b * CCH * NQ + q0;
    #pragma unroll
    for (int i = tid; i < 128 * 32; i += 256) {
        int d = i >> 5, j4 = (i & 31) * 4;
        float4 z  = *(float4*)&OT[d * 132 + j4];
        float4 xv = *(const float4*)&xb[(size_t)d * NQ + j4];
        float4 r  = make_float4(xv.x + z.x, xv.y + z.y, xv.z + z.z, xv.w + z.w);
        *(float4*)&ob[(size_t)d * NQ + j4] = r;
    }

    // self-reset: the LAST attn CTA zeroes all flags for the next (graph) launch.
    __syncthreads();
    if (tid == 0) {
        __threadfence();
        int old = atomicAdd(&g_attn_done, 1);
        if (old == ATTN_CTAS - 1) {
            #pragma unroll
            for (int i = 0; i < NB; i++) g_done[i] = 0;
            g_attn_done = 0;
            __threadfence();
        }
    }
}

// ===================== launch =====================
extern "C" void kernel_launch(void* const* d_in, const int* in_sizes, int n_in,
                              void* d_out, int out_size) {
    const float* x  = (const float*)d_in[0];
    const float* y  = (const float*)d_in[1];
    const float* Wq = (const float*)d_in[2];
    const float* bq = (const float*)d_in[3];
    const float* Wk = (const float*)d_in[4];
    const float* bk = (const float*)d_in[5];
    const float* Wv = (const float*)d_in[6];
    const float* bv = (const float*)d_in[7];
    float* out = (float*)d_out;

    cudaFuncSetAttribute(fused_kernel, cudaFuncAttributeMaxDynamicSharedMemorySize, FUSED_SMEM);
    fused_kernel<<<PROJ_CTAS + ATTN_CTAS, 256, FUSED_SMEM>>>(
        x, y, Wq, bq, Wk, bk, Wv, bv, out);
}